// round 8
// baseline (speedup 1.0000x reference)
#include <cuda_runtime.h>
#include <math.h>
#include <float.h>

#define B_    8
#define NPT   10000
#define FDIM  16
#define HDIM  128
#define NBINS 20
#define BINSZ 500
#define KTOP  5
#define EPB   (NPT*KTOP)    /* 50000 edges per batch */
#define TOTE  (B_*EPB)      /* 400000 edges total    */

typedef unsigned long long u64;

// packed fp32x2 FMA (Blackwell): 2 MACs per instruction, ptxas never auto-fuses
__device__ __forceinline__ u64 fma2(u64 a, u64 b, u64 c) {
    u64 d;
    asm("fma.rn.f32x2 %0, %1, %2, %3;" : "=l"(d) : "l"(a), "l"(b), "l"(c));
    return d;
}
__device__ __forceinline__ float2 unpack2(u64 v) {
    float2 f;
    asm("mov.b64 {%0, %1}, %2;" : "=f"(f.x), "=f"(f.y) : "l"(v));
    return f;
}
__device__ __forceinline__ u64 dup2(float x) {
    u64 d;
    asm("mov.b64 %0, {%1, %1};" : "=l"(d) : "f"(x));
    return d;
}

// ---------------- scratch (device globals: alloc-free) ----------------
__device__ float g_enc [B_*NPT*HDIM];   // ~41 MB
__device__ int   g_bin [B_*NPT];
__device__ int   g_hist[B_*NBINS];
__device__ int   g_perm[B_*NPT];
__device__ float g_topv[B_*NPT*KTOP];
__device__ int   g_topd[B_*NPT*KTOP];

// ---------------- K0: encoder MLP  (x:16 -> elu -> 128 -> 128) ----------------
// 50 points per block, 128 threads. W2 stored TRANSPOSED in smem with stride 132
// (pad) so thread j reads its output-row contiguously via LDS.128 -> f32x2 FMA.
#define EPTS 50
#define W2STR 132
__global__ void k_encoder(const float* __restrict__ x,
                          const float* __restrict__ W1, const float* __restrict__ b1,
                          const float* __restrict__ W2, const float* __restrict__ b2)
{
    extern __shared__ float sm[];
    float* W1s = sm;                        // 16*128 = 2048
    float* W2T = sm + 2048;                 // 128*132 = 16896 (transposed, padded)
    float* b1s = W2T + 128*W2STR;           // 128
    float* b2s = b1s + 128;                 // 128
    float* xs  = b2s + 128;                 // 50*16 = 800
    float* hs  = xs + EPTS*FDIM;            // 50*128 = 6400
    // total = 26400 floats = 105600 B

    const int tid = threadIdx.x;            // 128
    const int b   = blockIdx.y;
    const int pt0 = blockIdx.x * EPTS;
    const int j   = tid;

    for (int i = tid; i < 2048; i += 128) W1s[i] = W1[i];
    for (int i = tid; i < 16384; i += 128) {
        int d = i >> 7, jj = i & 127;
        W2T[jj*W2STR + d] = W2[i];          // transpose in smem
    }
    b1s[tid] = b1[tid];
    b2s[tid] = b2[tid];
    const float* xg = x + ((size_t)b*NPT + pt0)*FDIM;
    for (int i = tid; i < EPTS*FDIM; i += 128) xs[i] = xg[i];
    __syncthreads();

    // stage 1: h[p][j] = elu(x[p] @ W1[:,j] + b1[j]) for all 50 points
    const float bj = b1s[j];
    for (int p = 0; p < EPTS; p++) {
        float a = bj;
        const float* xp = xs + p*FDIM;
        #pragma unroll
        for (int f = 0; f < FDIM; f++)
            a = fmaf(xp[f], W1s[f*HDIM + j], a);
        hs[p*HDIM + j] = (a > 0.f) ? a : (__expf(a) - 1.f);
    }
    __syncthreads();

    // stage 2: enc[p][j] = h[p] @ W2T[j] + b2[j]  (packed f32x2, 2 points per pass
    // so each W2T LDS.128 feeds 4 fma2 -> fma-pipe-bound instead of issue-bound)
    const ulonglong2* wrow = (const ulonglong2*)(W2T + j*W2STR);  // 528B offset, 16B aligned
    const float b2j = b2s[j];
    float* eout = g_enc + ((size_t)b*NPT + pt0)*HDIM + j;
    for (int p = 0; p < EPTS; p += 2) {
        const ulonglong2* hp0 = (const ulonglong2*)(hs + p*HDIM);      // broadcast per warp
        const ulonglong2* hp1 = hp0 + 32;                              // next point
        u64 a00 = 0, a01 = 0, a10 = 0, a11 = 0;
        #pragma unroll
        for (int q = 0; q < 32; q++) {
            ulonglong2 wv = wrow[q];
            ulonglong2 h0 = hp0[q];
            ulonglong2 h1 = hp1[q];
            a00 = fma2(h0.x, wv.x, a00);
            a01 = fma2(h0.y, wv.y, a01);
            a10 = fma2(h1.x, wv.x, a10);
            a11 = fma2(h1.y, wv.y, a11);
        }
        float2 f00 = unpack2(a00), f01 = unpack2(a01);
        float2 f10 = unpack2(a10), f11 = unpack2(a11);
        eout[(size_t)p*HDIM]     = b2j + ((f00.x + f00.y) + (f01.x + f01.y));
        eout[(size_t)(p+1)*HDIM] = b2j + ((f10.x + f10.y) + (f11.x + f11.y));
    }
}

// ---------------- K1: zero histogram ----------------
__global__ void k_zero()
{
    int i = threadIdx.x;
    if (i < B_*NBINS) g_hist[i] = 0;
}

// ---------------- K2: bin assignment (argmax over [enc@R, -enc@R]) ----------------
__global__ void k_bins(const float* __restrict__ R)
{
    __shared__ float Rs[HDIM*10];
    const int tid = threadIdx.x;        // 256
    for (int i = tid; i < HDIM*10; i += 256) {
        int d = i / 10, c = i % 10;
        Rs[i] = R[d*100 + c];           // R is (128,100) row-major; first 10 cols
    }
    __syncthreads();

    const int wid = tid >> 5, lane = tid & 31;
    const int pg  = blockIdx.x*8 + wid;         // global point 0..79999
    const float4 ev = ((const float4*)(g_enc + (size_t)pg*HDIM))[lane];
    const int d0 = lane*4;

    float acc[10];
    #pragma unroll
    for (int c = 0; c < 10; c++) acc[c] = 0.f;
    #pragma unroll
    for (int c = 0; c < 10; c++) {
        acc[c] = fmaf(ev.x, Rs[(d0+0)*10 + c], acc[c]);
        acc[c] = fmaf(ev.y, Rs[(d0+1)*10 + c], acc[c]);
        acc[c] = fmaf(ev.z, Rs[(d0+2)*10 + c], acc[c]);
        acc[c] = fmaf(ev.w, Rs[(d0+3)*10 + c], acc[c]);
    }
    #pragma unroll
    for (int c = 0; c < 10; c++) {
        #pragma unroll
        for (int off = 16; off; off >>= 1)
            acc[c] += __shfl_xor_sync(0xffffffffu, acc[c], off);
    }
    if (lane == 0) {
        float best = acc[0];
        int   bi   = 0;
        #pragma unroll
        for (int i = 1; i < 20; i++) {
            float v = (i < 10) ? acc[i] : -acc[i-10];
            if (v > best) { best = v; bi = i; }    // strict > : JAX argmax tie rule
        }
        g_bin[pg] = bi;
        atomicAdd(&g_hist[(pg/NPT)*NBINS + bi], 1);
    }
}

// ---------------- K3: stable counting-sort scatter (1024 threads, 10 sweeps) ----------------
__global__ void k_scatter()
{
    const int b = blockIdx.y, v = blockIdx.x;
    const int tid = threadIdx.x, lane = tid & 31, wid = tid >> 5;  // 32 warps
    __shared__ int wcnt[32];
    __shared__ int sadd;

    int off = 0;
    for (int u = 0; u < v; u++) off += g_hist[b*NBINS + u];

    const int* bins = g_bin + b*NPT;
    for (int c0 = 0; c0 < NPT; c0 += 1024) {
        int p = c0 + tid;
        int m = (p < NPT) && (bins[p] == v);
        unsigned bal = __ballot_sync(0xffffffffu, m);
        int rank = __popc(bal & ((1u << lane) - 1u));
        if (lane == 0) wcnt[wid] = __popc(bal);
        __syncthreads();
        if (tid == 0) {
            int run = 0;
            for (int w = 0; w < 32; w++) { int t = wcnt[w]; wcnt[w] = run; run += t; }
            sadd = run;
        }
        __syncthreads();
        if (m) g_perm[b*NPT + off + wcnt[wid] + rank] = p;
        int add = sadd;
        __syncthreads();
        off += add;
    }
}

// ---------------- K4: per-tile P*P^T + per-row top-5 ----------------
// 2 threads per row, 64 dims each (32 u64 regs -> NO register spill under
// launch_bounds(256,2) 128-reg cap). shfl_xor(.,1) combines the half-dots;
// FP add commutativity makes both threads' dot bit-identical, so both keep
// identical top-5 state; the even thread writes.
#define TC 50
__global__ void __launch_bounds__(256, 2) k_main()
{
    __shared__ __align__(16) float colsm[TC*HDIM];   // 25.6 KB
    __shared__ int permsm[BINSZ];

    const int b     = blockIdx.y;
    const int t     = blockIdx.x >> 2;     // tile 0..19
    const int chunk = blockIdx.x & 3;      // row chunk 0..3 (128 rows each)
    const int tid   = threadIdx.x;         // 256

    for (int i = tid; i < BINSZ; i += 256)
        permsm[i] = g_perm[b*NPT + t*BINSZ + i];
    __syncthreads();

    const int row    = chunk*128 + (tid >> 1);
    const int sub    = tid & 1;            // which 64-dim half
    const bool valid = (row < BINSZ);
    const int rclamp = valid ? row : (BINSZ - 1);   // tail threads compute redundantly
    const int pr     = permsm[rclamp];

    u64 rowp[32];                          // 64 dims as 32 packed pairs = 64 regs
    {
        const ulonglong2* rp =
            (const ulonglong2*)(g_enc + ((size_t)b*NPT + pr)*HDIM + sub*64);
        #pragma unroll
        for (int i = 0; i < 16; i++) {
            ulonglong2 tld = rp[i];
            rowp[2*i]   = tld.x;
            rowp[2*i+1] = tld.y;
        }
    }

    float tv0=-FLT_MAX, tv1=-FLT_MAX, tv2=-FLT_MAX, tv3=-FLT_MAX, tv4=-FLT_MAX;
    int   ti0=0, ti1=0, ti2=0, ti3=0, ti4=0;

    for (int ct = 0; ct < BINSZ; ct += TC) {
        __syncthreads();
        for (int i = tid; i < TC*32; i += 256) {
            int c  = i >> 5;
            int dd = i & 31;
            ((float4*)colsm)[i] =
                ((const float4*)(g_enc + ((size_t)b*NPT + permsm[ct + c])*HDIM))[dd];
        }
        __syncthreads();

        for (int c = 0; c < TC; c++) {
            const ulonglong2* cp = (const ulonglong2*)(colsm + c*HDIM + sub*64);
            u64 a0 = 0, a1 = 0;
            #pragma unroll
            for (int q = 0; q < 16; q++) {
                ulonglong2 cv = cp[q];     // 2 addresses/warp -> broadcast within halves
                a0 = fma2(rowp[2*q],   cv.x, a0);
                a1 = fma2(rowp[2*q+1], cv.y, a1);
            }
            float2 f0 = unpack2(a0), f1 = unpack2(a1);
            float part  = (f0.x + f0.y) + (f1.x + f1.y);
            float other = __shfl_xor_sync(0xffffffffu, part, 1);
            float dot   = part + other;    // commutative -> identical in both threads
            if (dot > tv4) {               // strict >: lax.top_k tie rule
                int ci = ct + c;
                bool g0 = dot > tv0, g1 = dot > tv1, g2 = dot > tv2, g3 = dot > tv3;
                tv4 = g3 ? tv3 : dot;              ti4 = g3 ? ti3 : ci;
                tv3 = g3 ? (g2 ? tv2 : dot) : tv3; ti3 = g3 ? (g2 ? ti2 : ci) : ti3;
                tv2 = g2 ? (g1 ? tv1 : dot) : tv2; ti2 = g2 ? (g1 ? ti1 : ci) : ti2;
                tv1 = g1 ? (g0 ? tv0 : dot) : tv1; ti1 = g1 ? (g0 ? ti0 : ci) : ti1;
                tv0 = g0 ? dot : tv0;              ti0 = g0 ? ci  : ti0;
            }
        }
    }

    if (valid && sub == 0) {
        // map local top-k indices -> global dst, then sort 5 pairs by dst ascending
        int   d0 = permsm[ti0], d1 = permsm[ti1], d2 = permsm[ti2],
              d3 = permsm[ti3], d4 = permsm[ti4];
        float v0 = tv0, v1 = tv1, v2 = tv2, v3 = tv3, v4 = tv4;
        #define CSWAP(da, va, db, vb) do { \
            if (da > db) { int _t = da; da = db; db = _t; float _f = va; va = vb; vb = _f; } \
        } while (0)
        CSWAP(d0,v0,d1,v1); CSWAP(d1,v1,d2,v2); CSWAP(d2,v2,d3,v3); CSWAP(d3,v3,d4,v4);
        CSWAP(d0,v0,d1,v1); CSWAP(d1,v1,d2,v2); CSWAP(d2,v2,d3,v3);
        CSWAP(d0,v0,d1,v1); CSWAP(d1,v1,d2,v2);
        CSWAP(d0,v0,d1,v1);
        #undef CSWAP
        size_t base = ((size_t)b*NPT + pr)*KTOP;
        g_topd[base+0] = d0; g_topv[base+0] = 1.f/(1.f + __expf(-v0));
        g_topd[base+1] = d1; g_topv[base+1] = 1.f/(1.f + __expf(-v1));
        g_topd[base+2] = d2; g_topv[base+2] = 1.f/(1.f + __expf(-v2));
        g_topd[base+3] = d3; g_topv[base+3] = 1.f/(1.f + __expf(-v3));
        g_topd[base+4] = d4; g_topv[base+4] = 1.f/(1.f + __expf(-v4));
    }
}

// ---------------- K5: edge MLP (33 -> elu -> 128 -> 1 -> sigmoid) + output ----------------
// src-half of the first layer hoisted out of the 5-edge loop; f32x2 packed math.
__global__ void k_edges(const float* __restrict__ x,
                        const float* __restrict__ W1, const float* __restrict__ b1,
                        const float* __restrict__ W2, const float* __restrict__ b2,
                        float* __restrict__ out)
{
    __shared__ __align__(16) float W1s[33*HDIM];
    __shared__ __align__(16) float b1s[HDIM];
    __shared__ __align__(16) float W2s[HDIM];
    __shared__ float b2sh;

    const int tid = threadIdx.x;        // 256
    for (int i = tid; i < 33*HDIM; i += 256) W1s[i] = W1[i];
    if (tid < HDIM) { b1s[tid] = b1[tid]; W2s[tid] = W2[tid]; }
    if (tid == 0) b2sh = b2[0];
    __syncthreads();

    const int wid = tid >> 5, lane = tid & 31;
    const int pg  = blockIdx.x*8 + wid;       // source point 0..79999
    const int b   = pg / NPT;
    const int p   = pg % NPT;

    float xsv = 0.f;
    if (lane < FDIM) xsv = x[((size_t)b*NPT + p)*FDIM + lane];
    const ulonglong2 bj  = ((const ulonglong2*)b1s)[lane];
    const float4     w2v = ((const float4*)W2s)[lane];
    const float      b2v = b2sh;

    // hoisted src half: s = b1 + sum_f x_src[f] * W1[f]
    u64 s0 = bj.x, s1 = bj.y;
    #pragma unroll
    for (int f = 0; f < FDIM; f++) {
        float xv = __shfl_sync(0xffffffffu, xsv, f);
        u64 xp = dup2(xv);
        ulonglong2 w = ((const ulonglong2*)(W1s + f*HDIM))[lane];
        s0 = fma2(xp, w.x, s0);
        s1 = fma2(xp, w.y, s1);
    }

    for (int k = 0; k < KTOP; k++) {
        const int   dst = g_topd[(size_t)pg*KTOP + k];
        const float val = g_topv[(size_t)pg*KTOP + k];
        float xdv = 0.f;
        if (lane < FDIM) xdv = x[((size_t)b*NPT + dst)*FDIM + lane];

        u64 a0 = s0, a1 = s1;
        #pragma unroll
        for (int f = 0; f < FDIM; f++) {
            float xv = __shfl_sync(0xffffffffu, xdv, f);
            u64 xp = dup2(xv);
            ulonglong2 w = ((const ulonglong2*)(W1s + (16+f)*HDIM))[lane];
            a0 = fma2(xp, w.x, a0);
            a1 = fma2(xp, w.y, a1);
        }
        {
            u64 vp = dup2(val);
            ulonglong2 w = ((const ulonglong2*)(W1s + 32*HDIM))[lane];
            a0 = fma2(vp, w.x, a0);
            a1 = fma2(vp, w.y, a1);
        }
        float2 f0 = unpack2(a0), f1 = unpack2(a1);
        float h0 = (f0.x > 0.f) ? f0.x : (__expf(f0.x) - 1.f);
        float h1 = (f0.y > 0.f) ? f0.y : (__expf(f0.y) - 1.f);
        float h2 = (f1.x > 0.f) ? f1.x : (__expf(f1.x) - 1.f);
        float h3 = (f1.y > 0.f) ? f1.y : (__expf(f1.y) - 1.f);

        float partial = h0*w2v.x + h1*w2v.y + h2*w2v.z + h3*w2v.w;
        #pragma unroll
        for (int off = 16; off; off >>= 1)
            partial += __shfl_xor_sync(0xffffffffu, partial, off);

        if (lane == 0) {
            float e = 1.f / (1.f + __expf(-(partial + b2v)));
            size_t eidx = (size_t)b*EPB + (size_t)p*KTOP + k;
            out[eidx]          = e;            // edge_vals
            out[TOTE  + eidx]  = (float)p;     // src_idx
            out[2*TOTE + eidx] = (float)dst;   // dst_idx
        }
    }
}

// ---------------- launcher ----------------
extern "C" void kernel_launch(void* const* d_in, const int* in_sizes, int n_in,
                              void* d_out, int out_size)
{
    const float* x   = (const float*)d_in[0];
    const float* W1e = (const float*)d_in[1];
    const float* b1e = (const float*)d_in[2];
    const float* W2e = (const float*)d_in[3];
    const float* b2e = (const float*)d_in[4];
    const float* W1g = (const float*)d_in[5];
    const float* b1g = (const float*)d_in[6];
    const float* W2g = (const float*)d_in[7];
    const float* b2g = (const float*)d_in[8];
    const float* R   = (const float*)d_in[9];
    float* out = (float*)d_out;
    (void)in_sizes; (void)n_in; (void)out_size;

    const int smem0 = 26400 * (int)sizeof(float);   // 105,600 B dynamic smem for encoder
    cudaFuncSetAttribute(k_encoder, cudaFuncAttributeMaxDynamicSharedMemorySize, smem0);

    k_encoder<<<dim3(200, 8), 128, smem0>>>(x, W1e, b1e, W2e, b2e);
    k_zero   <<<1, 256>>>();
    k_bins   <<<10000, 256>>>(R);
    k_scatter<<<dim3(NBINS, B_), 1024>>>();
    k_main   <<<dim3(80, B_), 256>>>();
    k_edges  <<<10000, 256>>>(x, W1g, b1g, W2g, b2g, out);
}

// round 9
// speedup vs baseline: 1.3393x; 1.3393x over previous
#include <cuda_runtime.h>
#include <math.h>
#include <float.h>

#define B_    8
#define NPT   10000
#define FDIM  16
#define HDIM  128
#define NBINS 20
#define BINSZ 500
#define KTOP  5
#define EPB   (NPT*KTOP)    /* 50000 edges per batch */
#define TOTE  (B_*EPB)      /* 400000 edges total    */

typedef unsigned long long u64;

// packed fp32x2 FMA (Blackwell): 2 MACs per instruction, ptxas never auto-fuses
__device__ __forceinline__ u64 fma2(u64 a, u64 b, u64 c) {
    u64 d;
    asm("fma.rn.f32x2 %0, %1, %2, %3;" : "=l"(d) : "l"(a), "l"(b), "l"(c));
    return d;
}
__device__ __forceinline__ float2 unpack2(u64 v) {
    float2 f;
    asm("mov.b64 {%0, %1}, %2;" : "=f"(f.x), "=f"(f.y) : "l"(v));
    return f;
}
__device__ __forceinline__ u64 dup2(float x) {
    u64 d;
    asm("mov.b64 %0, {%1, %1};" : "=l"(d) : "f"(x));
    return d;
}

// ---------------- scratch (device globals: alloc-free) ----------------
__device__ float g_enc [B_*NPT*HDIM];   // ~41 MB
__device__ int   g_bin [B_*NPT];
__device__ int   g_hist[B_*NBINS];
__device__ int   g_perm[B_*NPT];
__device__ float g_topv[B_*NPT*KTOP];
__device__ int   g_topd[B_*NPT*KTOP];

// ---------------- K0: encoder MLP  (x:16 -> elu -> 128 -> 128) ----------------
// 50 points per block, 128 threads. W2 stored TRANSPOSED in smem with stride 132
// (pad) so thread j reads its output-row contiguously via LDS.128 -> f32x2 FMA.
#define EPTS 50
#define W2STR 132
__global__ void k_encoder(const float* __restrict__ x,
                          const float* __restrict__ W1, const float* __restrict__ b1,
                          const float* __restrict__ W2, const float* __restrict__ b2)
{
    extern __shared__ float sm[];
    float* W1s = sm;                        // 16*128 = 2048
    float* W2T = sm + 2048;                 // 128*132 = 16896 (transposed, padded)
    float* b1s = W2T + 128*W2STR;           // 128
    float* b2s = b1s + 128;                 // 128
    float* xs  = b2s + 128;                 // 50*16 = 800
    float* hs  = xs + EPTS*FDIM;            // 50*128 = 6400
    // total = 26400 floats = 105600 B

    const int tid = threadIdx.x;            // 128
    const int b   = blockIdx.y;
    const int pt0 = blockIdx.x * EPTS;
    const int j   = tid;

    for (int i = tid; i < 2048; i += 128) W1s[i] = W1[i];
    for (int i = tid; i < 16384; i += 128) {
        int d = i >> 7, jj = i & 127;
        W2T[jj*W2STR + d] = W2[i];          // transpose in smem
    }
    b1s[tid] = b1[tid];
    b2s[tid] = b2[tid];
    const float* xg = x + ((size_t)b*NPT + pt0)*FDIM;
    for (int i = tid; i < EPTS*FDIM; i += 128) xs[i] = xg[i];
    __syncthreads();

    // stage 1: h[p][j] = elu(x[p] @ W1[:,j] + b1[j]) for all 50 points
    const float bj = b1s[j];
    for (int p = 0; p < EPTS; p++) {
        float a = bj;
        const float* xp = xs + p*FDIM;
        #pragma unroll
        for (int f = 0; f < FDIM; f++)
            a = fmaf(xp[f], W1s[f*HDIM + j], a);
        hs[p*HDIM + j] = (a > 0.f) ? a : (__expf(a) - 1.f);
    }
    __syncthreads();

    // stage 2: enc[p][j] = h[p] @ W2T[j] + b2[j]  (packed f32x2)
    const ulonglong2* wrow = (const ulonglong2*)(W2T + j*W2STR);  // 528B offset, 16B aligned
    const float b2j = b2s[j];
    float* eout = g_enc + ((size_t)b*NPT + pt0)*HDIM + j;
    for (int p = 0; p < EPTS; p++) {
        const ulonglong2* hp = (const ulonglong2*)(hs + p*HDIM);  // broadcast per warp
        u64 a0 = 0, a1 = 0;
        #pragma unroll
        for (int q = 0; q < 32; q++) {
            ulonglong2 hv = hp[q];
            ulonglong2 wv = wrow[q];
            a0 = fma2(hv.x, wv.x, a0);
            a1 = fma2(hv.y, wv.y, a1);
        }
        float2 f0 = unpack2(a0), f1 = unpack2(a1);
        eout[(size_t)p*HDIM] = b2j + ((f0.x + f0.y) + (f1.x + f1.y));
    }
}

// ---------------- K1: zero histogram ----------------
__global__ void k_zero()
{
    int i = threadIdx.x;
    if (i < B_*NBINS) g_hist[i] = 0;
}

// ---------------- K2: bin assignment (argmax over [enc@R, -enc@R]) ----------------
__global__ void k_bins(const float* __restrict__ R)
{
    __shared__ float Rs[HDIM*10];
    const int tid = threadIdx.x;        // 256
    for (int i = tid; i < HDIM*10; i += 256) {
        int d = i / 10, c = i % 10;
        Rs[i] = R[d*100 + c];           // R is (128,100) row-major; first 10 cols
    }
    __syncthreads();

    const int wid = tid >> 5, lane = tid & 31;
    const int pg  = blockIdx.x*8 + wid;         // global point 0..79999
    const float4 ev = ((const float4*)(g_enc + (size_t)pg*HDIM))[lane];
    const int d0 = lane*4;

    float acc[10];
    #pragma unroll
    for (int c = 0; c < 10; c++) acc[c] = 0.f;
    #pragma unroll
    for (int c = 0; c < 10; c++) {
        acc[c] = fmaf(ev.x, Rs[(d0+0)*10 + c], acc[c]);
        acc[c] = fmaf(ev.y, Rs[(d0+1)*10 + c], acc[c]);
        acc[c] = fmaf(ev.z, Rs[(d0+2)*10 + c], acc[c]);
        acc[c] = fmaf(ev.w, Rs[(d0+3)*10 + c], acc[c]);
    }
    #pragma unroll
    for (int c = 0; c < 10; c++) {
        #pragma unroll
        for (int off = 16; off; off >>= 1)
            acc[c] += __shfl_xor_sync(0xffffffffu, acc[c], off);
    }
    if (lane == 0) {
        float best = acc[0];
        int   bi   = 0;
        #pragma unroll
        for (int i = 1; i < 20; i++) {
            float v = (i < 10) ? acc[i] : -acc[i-10];
            if (v > best) { best = v; bi = i; }    // strict > : JAX argmax tie rule
        }
        g_bin[pg] = bi;
        atomicAdd(&g_hist[(pg/NPT)*NBINS + bi], 1);
    }
}

// ---------------- K3: stable counting-sort scatter (1024 threads, 10 sweeps) ----------------
__global__ void k_scatter()
{
    const int b = blockIdx.y, v = blockIdx.x;
    const int tid = threadIdx.x, lane = tid & 31, wid = tid >> 5;  // 32 warps
    __shared__ int wcnt[32];
    __shared__ int sadd;

    int off = 0;
    for (int u = 0; u < v; u++) off += g_hist[b*NBINS + u];

    const int* bins = g_bin + b*NPT;
    for (int c0 = 0; c0 < NPT; c0 += 1024) {
        int p = c0 + tid;
        int m = (p < NPT) && (bins[p] == v);
        unsigned bal = __ballot_sync(0xffffffffu, m);
        int rank = __popc(bal & ((1u << lane) - 1u));
        if (lane == 0) wcnt[wid] = __popc(bal);
        __syncthreads();
        if (tid == 0) {
            int run = 0;
            for (int w = 0; w < 32; w++) { int t = wcnt[w]; wcnt[w] = run; run += t; }
            sadd = run;
        }
        __syncthreads();
        if (m) g_perm[b*NPT + off + wcnt[wid] + rank] = p;
        int add = sadd;
        __syncthreads();
        off += add;
    }
}

// ---------------- K4: per-tile P*P^T + per-row top-5 (f32x2, 125 rows/block) ----------------
// ONE thread per row, full 128-dim row in registers (64 u64 = 128 regs).
// launch_bounds(128,2) -> 256-reg cap: guaranteed NO spill (R6 used (128,3)=170
// cap, borderline). 8 warps/SM; 2 fma2 chains/thread meet lat4@rt2 -> fma-bound.
#define TC 50
#define RCHUNK 125
__global__ void __launch_bounds__(128, 2) k_main()
{
    __shared__ __align__(16) float colsm[TC*HDIM];   // 25.6 KB
    __shared__ int permsm[BINSZ];

    const int b     = blockIdx.y;
    const int t     = blockIdx.x >> 2;     // tile 0..19
    const int chunk = blockIdx.x & 3;      // row chunk 0..3
    const int tid   = threadIdx.x;         // 128

    for (int i = tid; i < BINSZ; i += 128)
        permsm[i] = g_perm[b*NPT + t*BINSZ + i];
    __syncthreads();

    const int  r      = chunk*RCHUNK + tid;
    const bool active = (tid < RCHUNK);

    u64 rowp[64];                          // 128 dims as 64 packed pairs
    int pr = 0;
    if (active) {
        pr = permsm[r];
        const ulonglong2* rp = (const ulonglong2*)(g_enc + ((size_t)b*NPT + pr)*HDIM);
        #pragma unroll
        for (int i = 0; i < 32; i++) {
            ulonglong2 tld = rp[i];
            rowp[2*i]   = tld.x;
            rowp[2*i+1] = tld.y;
        }
    }

    float tv0=-FLT_MAX, tv1=-FLT_MAX, tv2=-FLT_MAX, tv3=-FLT_MAX, tv4=-FLT_MAX;
    int   ti0=0, ti1=0, ti2=0, ti3=0, ti4=0;

    for (int ct = 0; ct < BINSZ; ct += TC) {
        __syncthreads();
        for (int i = tid; i < TC*32; i += 128) {
            int c  = i >> 5;
            int dd = i & 31;
            ((float4*)colsm)[i] =
                ((const float4*)(g_enc + ((size_t)b*NPT + permsm[ct + c])*HDIM))[dd];
        }
        __syncthreads();

        if (active) {
            for (int c = 0; c < TC; c++) {
                const ulonglong2* cp = (const ulonglong2*)(colsm + c*HDIM);
                u64 a0 = 0, a1 = 0;
                #pragma unroll
                for (int q = 0; q < 32; q++) {
                    ulonglong2 cv = cp[q];            // uniform per warp -> broadcast LDS
                    a0 = fma2(rowp[2*q],   cv.x, a0);
                    a1 = fma2(rowp[2*q+1], cv.y, a1);
                }
                float2 f0 = unpack2(a0), f1 = unpack2(a1);
                float dot = (f0.x + f0.y) + (f1.x + f1.y);
                if (dot > tv4) {                      // strict >: lax.top_k tie rule
                    int ci = ct + c;
                    bool g0 = dot > tv0, g1 = dot > tv1, g2 = dot > tv2, g3 = dot > tv3;
                    tv4 = g3 ? tv3 : dot;              ti4 = g3 ? ti3 : ci;
                    tv3 = g3 ? (g2 ? tv2 : dot) : tv3; ti3 = g3 ? (g2 ? ti2 : ci) : ti3;
                    tv2 = g2 ? (g1 ? tv1 : dot) : tv2; ti2 = g2 ? (g1 ? ti1 : ci) : ti2;
                    tv1 = g1 ? (g0 ? tv0 : dot) : tv1; ti1 = g1 ? (g0 ? ti0 : ci) : ti1;
                    tv0 = g0 ? dot : tv0;              ti0 = g0 ? ci  : ti0;
                }
            }
        }
    }

    if (active) {
        // map local top-k indices -> global dst, then sort 5 pairs by dst ascending
        int   d0 = permsm[ti0], d1 = permsm[ti1], d2 = permsm[ti2],
              d3 = permsm[ti3], d4 = permsm[ti4];
        float v0 = tv0, v1 = tv1, v2 = tv2, v3 = tv3, v4 = tv4;
        #define CSWAP(da, va, db, vb) do { \
            if (da > db) { int _t = da; da = db; db = _t; float _f = va; va = vb; vb = _f; } \
        } while (0)
        CSWAP(d0,v0,d1,v1); CSWAP(d1,v1,d2,v2); CSWAP(d2,v2,d3,v3); CSWAP(d3,v3,d4,v4);
        CSWAP(d0,v0,d1,v1); CSWAP(d1,v1,d2,v2); CSWAP(d2,v2,d3,v3);
        CSWAP(d0,v0,d1,v1); CSWAP(d1,v1,d2,v2);
        CSWAP(d0,v0,d1,v1);
        #undef CSWAP
        size_t base = ((size_t)b*NPT + pr)*KTOP;
        g_topd[base+0] = d0; g_topv[base+0] = 1.f/(1.f + __expf(-v0));
        g_topd[base+1] = d1; g_topv[base+1] = 1.f/(1.f + __expf(-v1));
        g_topd[base+2] = d2; g_topv[base+2] = 1.f/(1.f + __expf(-v2));
        g_topd[base+3] = d3; g_topv[base+3] = 1.f/(1.f + __expf(-v3));
        g_topd[base+4] = d4; g_topv[base+4] = 1.f/(1.f + __expf(-v4));
    }
}

// ---------------- K5: edge MLP (33 -> elu -> 128 -> 1 -> sigmoid) + output ----------------
// src-half of the first layer hoisted out of the 5-edge loop; f32x2 packed math.
__global__ void k_edges(const float* __restrict__ x,
                        const float* __restrict__ W1, const float* __restrict__ b1,
                        const float* __restrict__ W2, const float* __restrict__ b2,
                        float* __restrict__ out)
{
    __shared__ __align__(16) float W1s[33*HDIM];
    __shared__ __align__(16) float b1s[HDIM];
    __shared__ __align__(16) float W2s[HDIM];
    __shared__ float b2sh;

    const int tid = threadIdx.x;        // 256
    for (int i = tid; i < 33*HDIM; i += 256) W1s[i] = W1[i];
    if (tid < HDIM) { b1s[tid] = b1[tid]; W2s[tid] = W2[tid]; }
    if (tid == 0) b2sh = b2[0];
    __syncthreads();

    const int wid = tid >> 5, lane = tid & 31;
    const int pg  = blockIdx.x*8 + wid;       // source point 0..79999
    const int b   = pg / NPT;
    const int p   = pg % NPT;

    float xsv = 0.f;
    if (lane < FDIM) xsv = x[((size_t)b*NPT + p)*FDIM + lane];
    const ulonglong2 bj  = ((const ulonglong2*)b1s)[lane];
    const float4     w2v = ((const float4*)W2s)[lane];
    const float      b2v = b2sh;

    // hoisted src half: s = b1 + sum_f x_src[f] * W1[f]
    u64 s0 = bj.x, s1 = bj.y;
    #pragma unroll
    for (int f = 0; f < FDIM; f++) {
        float xv = __shfl_sync(0xffffffffu, xsv, f);
        u64 xp = dup2(xv);
        ulonglong2 w = ((const ulonglong2*)(W1s + f*HDIM))[lane];
        s0 = fma2(xp, w.x, s0);
        s1 = fma2(xp, w.y, s1);
    }

    for (int k = 0; k < KTOP; k++) {
        const int   dst = g_topd[(size_t)pg*KTOP + k];
        const float val = g_topv[(size_t)pg*KTOP + k];
        float xdv = 0.f;
        if (lane < FDIM) xdv = x[((size_t)b*NPT + dst)*FDIM + lane];

        u64 a0 = s0, a1 = s1;
        #pragma unroll
        for (int f = 0; f < FDIM; f++) {
            float xv = __shfl_sync(0xffffffffu, xdv, f);
            u64 xp = dup2(xv);
            ulonglong2 w = ((const ulonglong2*)(W1s + (16+f)*HDIM))[lane];
            a0 = fma2(xp, w.x, a0);
            a1 = fma2(xp, w.y, a1);
        }
        {
            u64 vp = dup2(val);
            ulonglong2 w = ((const ulonglong2*)(W1s + 32*HDIM))[lane];
            a0 = fma2(vp, w.x, a0);
            a1 = fma2(vp, w.y, a1);
        }
        float2 f0 = unpack2(a0), f1 = unpack2(a1);
        float h0 = (f0.x > 0.f) ? f0.x : (__expf(f0.x) - 1.f);
        float h1 = (f0.y > 0.f) ? f0.y : (__expf(f0.y) - 1.f);
        float h2 = (f1.x > 0.f) ? f1.x : (__expf(f1.x) - 1.f);
        float h3 = (f1.y > 0.f) ? f1.y : (__expf(f1.y) - 1.f);

        float partial = h0*w2v.x + h1*w2v.y + h2*w2v.z + h3*w2v.w;
        #pragma unroll
        for (int off = 16; off; off >>= 1)
            partial += __shfl_xor_sync(0xffffffffu, partial, off);

        if (lane == 0) {
            float e = 1.f / (1.f + __expf(-(partial + b2v)));
            size_t eidx = (size_t)b*EPB + (size_t)p*KTOP + k;
            out[eidx]          = e;            // edge_vals
            out[TOTE  + eidx]  = (float)p;     // src_idx
            out[2*TOTE + eidx] = (float)dst;   // dst_idx
        }
    }
}

// ---------------- launcher ----------------
extern "C" void kernel_launch(void* const* d_in, const int* in_sizes, int n_in,
                              void* d_out, int out_size)
{
    const float* x   = (const float*)d_in[0];
    const float* W1e = (const float*)d_in[1];
    const float* b1e = (const float*)d_in[2];
    const float* W2e = (const float*)d_in[3];
    const float* b2e = (const float*)d_in[4];
    const float* W1g = (const float*)d_in[5];
    const float* b1g = (const float*)d_in[6];
    const float* W2g = (const float*)d_in[7];
    const float* b2g = (const float*)d_in[8];
    const float* R   = (const float*)d_in[9];
    float* out = (float*)d_out;
    (void)in_sizes; (void)n_in; (void)out_size;

    const int smem0 = 26400 * (int)sizeof(float);   // 105,600 B dynamic smem for encoder
    cudaFuncSetAttribute(k_encoder, cudaFuncAttributeMaxDynamicSharedMemorySize, smem0);

    k_encoder<<<dim3(200, 8), 128, smem0>>>(x, W1e, b1e, W2e, b2e);
    k_zero   <<<1, 256>>>();
    k_bins   <<<10000, 256>>>(R);
    k_scatter<<<dim3(NBINS, B_), 1024>>>();
    k_main   <<<dim3(80, B_), 128>>>();
    k_edges  <<<10000, 256>>>(x, W1g, b1g, W2g, b2g, out);
}